// round 4
// baseline (speedup 1.0000x reference)
#include <cuda_runtime.h>
#include <cuda_bf16.h>
#include <cstdint>

#define E_ 8
#define T_ 16384
#define D_ 2048
#define H_ 1024

// ---------------- scratch (__device__ globals; runtime alloc forbidden) ------
__device__ __align__(1024) float g_x [T_ * (size_t)D_];    // tf32(x)
__device__ __align__(1024) float g_w1[E_ * (size_t)H_ * D_];
__device__ __align__(1024) float g_w3[E_ * (size_t)H_ * D_];
__device__ __align__(1024) float g_w2[E_ * (size_t)D_ * H_];
__device__ __align__(1024) float g_h [T_ * (size_t)H_];    // tf32(h)

// ---------------- helpers ----------------
__device__ __forceinline__ uint32_t smem_u32(const void* p) {
    uint32_t a;
    asm("{ .reg .u64 t; cvta.to.shared.u64 t, %1; cvt.u32.u64 %0, t; }" : "=r"(a) : "l"(p));
    return a;
}
__device__ __forceinline__ float rna_tf32(float x) {
    uint32_t r;
    asm("cvt.rna.tf32.f32 %0, %1;" : "=r"(r) : "f"(x));
    return __uint_as_float(r);
}
__device__ __forceinline__ void cp16(float* sdst, const float* gsrc) {
    uint32_t s = smem_u32(sdst);
    asm volatile("cp.async.cg.shared.global [%0], [%1], 16;" :: "r"(s), "l"(gsrc) : "memory");
}
__device__ __forceinline__ void cp_commit() {
    asm volatile("cp.async.commit_group;" ::: "memory");
}
__device__ __forceinline__ void mma_tf32(float* c, const uint32_t* a, const uint32_t* b) {
    asm volatile(
        "mma.sync.aligned.m16n8k8.row.col.f32.tf32.tf32.f32 "
        "{%0,%1,%2,%3}, {%4,%5,%6,%7}, {%8,%9}, {%0,%1,%2,%3};"
        : "+f"(c[0]), "+f"(c[1]), "+f"(c[2]), "+f"(c[3])
        : "r"(a[0]), "r"(a[1]), "r"(a[2]), "r"(a[3]), "r"(b[0]), "r"(b[1]));
}
__device__ __forceinline__ float silu(float a) { return a / (1.f + __expf(-a)); }

// SMEM row stride: 36 floats (144 B = 16B aligned; fragment banks = 4g+t, conflict-free)
#define RS 36
#define STG_FLOATS 9216            // per-stage floats (A 4608 + 2*2304 or A+B 4608+4608)
#define SMEM_SZ (2 * STG_FLOATS * 4)

// ---------------- pack: fp32 -> rna tf32, same layout -------------------------
__global__ void cvt_rna_kernel(const float4* __restrict__ in, int which, int n4) {
    int i = blockIdx.x * blockDim.x + threadIdx.x;
    if (i >= n4) return;
    float4* out = (which == 0) ? (float4*)g_x  :
                  (which == 1) ? (float4*)g_w1 :
                  (which == 2) ? (float4*)g_w3 : (float4*)g_w2;
    float4 v = in[i];
    v.x = rna_tf32(v.x); v.y = rna_tf32(v.y); v.z = rna_tf32(v.z); v.w = rna_tf32(v.w);
    out[i] = v;
}

// ---------------- GEMM1: h = rna( silu(x@w1^T) * (x@w3^T) ) -------------------
// BM=128, BN=64 per weight, BK=32; grid 2048 = E(8) x mt(16) x nt(16); 256 thr
__global__ void __launch_bounds__(256, 1) moe_gemm1() {
    extern __shared__ float sm[];
    const int tid = threadIdx.x, lane = tid & 31, wid = tid >> 5;
    const int g = lane >> 2, t = lane & 3;
    const int bx = blockIdx.x;
    const int e = bx >> 8, mt = (bx >> 4) & 15, nt = bx & 15;
    const int m0 = e * 2048 + mt * 128, n0 = nt * 64;
    const float* A  = g_x  + (size_t)m0 * D_;
    const float* B1 = g_w1 + (size_t)(e * H_ + n0) * D_;
    const float* B3 = g_w3 + (size_t)(e * H_ + n0) * D_;
    const int KIT = D_ / 32;  // 64

    const int m_off = (wid & 3) * 32, n_off = (wid >> 2) * 32;
    float c1[2][4][4], c3[2][4][4];
    #pragma unroll
    for (int i = 0; i < 2; ++i)
        #pragma unroll
        for (int j = 0; j < 4; ++j)
            #pragma unroll
            for (int q = 0; q < 4; ++q) { c1[i][j][q] = 0.f; c3[i][j][q] = 0.f; }

    auto issue = [&](int s, int kt) {
        float* dst = sm + s * STG_FLOATS;
        const int koff = kt * 32;
        #pragma unroll
        for (int i = 0; i < 4; ++i) {               // A: 128 rows x 8 float4
            int idx = tid + 256 * i, r = idx >> 3, c = idx & 7;
            cp16(dst + r * RS + c * 4, A + (size_t)r * D_ + koff + c * 4);
        }
        float* d1 = dst + 4608;
        #pragma unroll
        for (int i = 0; i < 2; ++i) {               // B1: 64 rows x 8 float4
            int idx = tid + 256 * i, r = idx >> 3, c = idx & 7;
            cp16(d1 + r * RS + c * 4, B1 + (size_t)r * D_ + koff + c * 4);
        }
        float* d3 = dst + 6912;
        #pragma unroll
        for (int i = 0; i < 2; ++i) {               // B3
            int idx = tid + 256 * i, r = idx >> 3, c = idx & 7;
            cp16(d3 + r * RS + c * 4, B3 + (size_t)r * D_ + koff + c * 4);
        }
        cp_commit();
    };

    issue(0, 0);
    for (int kt = 0; kt < KIT; ++kt) {
        int cur = kt & 1;
        if (kt + 1 < KIT) {
            issue(cur ^ 1, kt + 1);
            asm volatile("cp.async.wait_group 1;" ::: "memory");
        } else {
            asm volatile("cp.async.wait_group 0;" ::: "memory");
        }
        __syncthreads();
        const float* As  = sm + cur * STG_FLOATS;
        const float* B1s = As + 4608;
        const float* B3s = As + 6912;
        #pragma unroll
        for (int kk = 0; kk < 4; ++kk) {
            const int k0 = kk * 8;
            uint32_t a[2][4], b1f[4][2], b3f[4][2];
            #pragma unroll
            for (int mi = 0; mi < 2; ++mi) {
                const float* ap = As + (m_off + 16 * mi + g) * RS + k0 + t;
                a[mi][0] = __float_as_uint(ap[0]);
                a[mi][2] = __float_as_uint(ap[4]);
                a[mi][1] = __float_as_uint(ap[8 * RS]);
                a[mi][3] = __float_as_uint(ap[8 * RS + 4]);
            }
            #pragma unroll
            for (int nj = 0; nj < 4; ++nj) {
                const float* bp = B1s + (n_off + 8 * nj + g) * RS + k0 + t;
                b1f[nj][0] = __float_as_uint(bp[0]);
                b1f[nj][1] = __float_as_uint(bp[4]);
                const float* bq = B3s + (n_off + 8 * nj + g) * RS + k0 + t;
                b3f[nj][0] = __float_as_uint(bq[0]);
                b3f[nj][1] = __float_as_uint(bq[4]);
            }
            #pragma unroll
            for (int mi = 0; mi < 2; ++mi)
                #pragma unroll
                for (int nj = 0; nj < 4; ++nj) {
                    mma_tf32(c1[mi][nj], a[mi], b1f[nj]);
                    mma_tf32(c3[mi][nj], a[mi], b3f[nj]);
                }
        }
        __syncthreads();
    }

    // epilogue: h = rna(silu(c1) * c3), float2 stores
    #pragma unroll
    for (int mi = 0; mi < 2; ++mi)
        #pragma unroll
        for (int nj = 0; nj < 4; ++nj) {
            int r0 = m0 + m_off + 16 * mi + g;
            int col = n0 + n_off + 8 * nj + 2 * t;
            float2 v;
            v.x = rna_tf32(silu(c1[mi][nj][0]) * c3[mi][nj][0]);
            v.y = rna_tf32(silu(c1[mi][nj][1]) * c3[mi][nj][1]);
            *(float2*)(g_h + (size_t)r0 * H_ + col) = v;
            v.x = rna_tf32(silu(c1[mi][nj][2]) * c3[mi][nj][2]);
            v.y = rna_tf32(silu(c1[mi][nj][3]) * c3[mi][nj][3]);
            *(float2*)(g_h + (size_t)(r0 + 8) * H_ + col) = v;
        }
}

// ---------------- GEMM2: out = h @ w2^T ---------------------------------------
// BM=128, BN=128, BK=32, K=1024; grid 2048 = E(8) x mt(16) x nt(16); 256 thr
__global__ void __launch_bounds__(256, 1) moe_gemm2(float* __restrict__ out) {
    extern __shared__ float sm[];
    const int tid = threadIdx.x, lane = tid & 31, wid = tid >> 5;
    const int g = lane >> 2, t = lane & 3;
    const int bx = blockIdx.x;
    const int e = bx >> 8, mt = (bx >> 4) & 15, nt = bx & 15;
    const int m0 = e * 2048 + mt * 128, n0 = nt * 128;
    const float* A = g_h  + (size_t)m0 * H_;
    const float* B = g_w2 + (size_t)((size_t)e * D_ + n0) * H_;
    const int KIT = H_ / 32;  // 32

    const int m_off = (wid & 3) * 32, n_off = (wid >> 2) * 64;
    float cc[2][8][4];
    #pragma unroll
    for (int i = 0; i < 2; ++i)
        #pragma unroll
        for (int j = 0; j < 8; ++j)
            #pragma unroll
            for (int q = 0; q < 4; ++q) cc[i][j][q] = 0.f;

    auto issue = [&](int s, int kt) {
        float* dst = sm + s * STG_FLOATS;
        const int koff = kt * 32;
        #pragma unroll
        for (int i = 0; i < 4; ++i) {               // A: 128 x 8 float4
            int idx = tid + 256 * i, r = idx >> 3, c = idx & 7;
            cp16(dst + r * RS + c * 4, A + (size_t)r * H_ + koff + c * 4);
        }
        float* db = dst + 4608;
        #pragma unroll
        for (int i = 0; i < 4; ++i) {               // B: 128 x 8 float4
            int idx = tid + 256 * i, r = idx >> 3, c = idx & 7;
            cp16(db + r * RS + c * 4, B + (size_t)r * H_ + koff + c * 4);
        }
        cp_commit();
    };

    issue(0, 0);
    for (int kt = 0; kt < KIT; ++kt) {
        int cur = kt & 1;
        if (kt + 1 < KIT) {
            issue(cur ^ 1, kt + 1);
            asm volatile("cp.async.wait_group 1;" ::: "memory");
        } else {
            asm volatile("cp.async.wait_group 0;" ::: "memory");
        }
        __syncthreads();
        const float* As = sm + cur * STG_FLOATS;
        const float* Bs = As + 4608;
        #pragma unroll
        for (int kk = 0; kk < 4; ++kk) {
            const int k0 = kk * 8;
            uint32_t a[2][4], bf[8][2];
            #pragma unroll
            for (int mi = 0; mi < 2; ++mi) {
                const float* ap = As + (m_off + 16 * mi + g) * RS + k0 + t;
                a[mi][0] = __float_as_uint(ap[0]);
                a[mi][2] = __float_as_uint(ap[4]);
                a[mi][1] = __float_as_uint(ap[8 * RS]);
                a[mi][3] = __float_as_uint(ap[8 * RS + 4]);
            }
            #pragma unroll
            for (int nj = 0; nj < 8; ++nj) {
                const float* bp = Bs + (n_off + 8 * nj + g) * RS + k0 + t;
                bf[nj][0] = __float_as_uint(bp[0]);
                bf[nj][1] = __float_as_uint(bp[4]);
            }
            #pragma unroll
            for (int mi = 0; mi < 2; ++mi)
                #pragma unroll
                for (int nj = 0; nj < 8; ++nj)
                    mma_tf32(cc[mi][nj], a[mi], bf[nj]);
        }
        __syncthreads();
    }

    #pragma unroll
    for (int mi = 0; mi < 2; ++mi)
        #pragma unroll
        for (int nj = 0; nj < 8; ++nj) {
            int r0 = m0 + m_off + 16 * mi + g;
            int col = n0 + n_off + 8 * nj + 2 * t;
            float2 v;
            v.x = cc[mi][nj][0]; v.y = cc[mi][nj][1];
            *(float2*)(out + (size_t)r0 * D_ + col) = v;
            v.x = cc[mi][nj][2]; v.y = cc[mi][nj][3];
            *(float2*)(out + (size_t)(r0 + 8) * D_ + col) = v;
        }
}

// ---------------- launch ----------------
extern "C" void kernel_launch(void* const* d_in, const int* in_sizes, int n_in,
                              void* d_out, int out_size) {
    const float4* x  = (const float4*)d_in[0];
    const float4* w1 = (const float4*)d_in[2];
    const float4* w2 = (const float4*)d_in[3];
    const float4* w3 = (const float4*)d_in[4];
    float* out = (float*)d_out;

    int T4 = (int)((size_t)T_ * D_ / 4);      // 8388608
    int W4 = (int)((size_t)E_ * H_ * D_ / 4); // 4194304

    cvt_rna_kernel<<<T4 / 256, 256>>>(x,  0, T4);
    cvt_rna_kernel<<<W4 / 256, 256>>>(w1, 1, W4);
    cvt_rna_kernel<<<W4 / 256, 256>>>(w3, 2, W4);
    cvt_rna_kernel<<<W4 / 256, 256>>>(w2, 3, W4);

    cudaFuncSetAttribute(moe_gemm1, cudaFuncAttributeMaxDynamicSharedMemorySize, SMEM_SZ);
    cudaFuncSetAttribute(moe_gemm2, cudaFuncAttributeMaxDynamicSharedMemorySize, SMEM_SZ);

    moe_gemm1<<<2048, 256, SMEM_SZ>>>();
    moe_gemm2<<<2048, 256, SMEM_SZ>>>(out);
}

// round 5
// speedup vs baseline: 1.2301x; 1.2301x over previous
#include <cuda_runtime.h>
#include <cuda_bf16.h>
#include <cstdint>

#define E_ 8
#define T_ 16384
#define D_ 2048
#define H_ 1024

// ---------------- scratch (__device__ globals; runtime alloc forbidden) ------
// All operand tensors live here in tf32(rna) precision with columns permuted
// within each 8-col K-group: [0,4,1,5,2,6,3,7]  (fragment pairs adjacent).
__device__ __align__(1024) float g_x [T_ * (size_t)D_];
__device__ __align__(1024) float g_w1[E_ * (size_t)H_ * D_];
__device__ __align__(1024) float g_w3[E_ * (size_t)H_ * D_];
__device__ __align__(1024) float g_w2[E_ * (size_t)D_ * H_];
__device__ __align__(1024) float g_h [T_ * (size_t)H_];

// ---------------- helpers ----------------
__device__ __forceinline__ uint32_t smem_u32(const void* p) {
    uint32_t a;
    asm("{ .reg .u64 t; cvta.to.shared.u64 t, %1; cvt.u32.u64 %0, t; }" : "=r"(a) : "l"(p));
    return a;
}
__device__ __forceinline__ float rna_tf32(float x) {
    uint32_t r;
    asm("cvt.rna.tf32.f32 %0, %1;" : "=r"(r) : "f"(x));
    return __uint_as_float(r);
}
__device__ __forceinline__ void cp16(float* sdst, const float* gsrc) {
    uint32_t s = smem_u32(sdst);
    asm volatile("cp.async.cg.shared.global [%0], [%1], 16;" :: "r"(s), "l"(gsrc) : "memory");
}
__device__ __forceinline__ void mma_tf32(float* c, const uint32_t* a, const uint32_t* b) {
    asm volatile(
        "mma.sync.aligned.m16n8k8.row.col.f32.tf32.tf32.f32 "
        "{%0,%1,%2,%3}, {%4,%5,%6,%7}, {%8,%9}, {%0,%1,%2,%3};"
        : "+f"(c[0]), "+f"(c[1]), "+f"(c[2]), "+f"(c[3])
        : "r"(a[0]), "r"(a[1]), "r"(a[2]), "r"(a[3]), "r"(b[0]), "r"(b[1]));
}
__device__ __forceinline__ float silu(float a) { return a / (1.f + __expf(-a)); }

// SMEM row stride 40 floats (160B): bank(40g+2t)=8g+2t mod 32 -> conflict-free
// LDS.64 fragment loads in both 16-lane phases.
#define RS 40
#define STG_FLOATS 15360        // A 256*40 + B 128*40 (or 64*40*2)
#define SMEM_SZ (2 * STG_FLOATS * 4)

// ---------------- pack: fp32 -> rna tf32 + pair permutation -------------------
// Each thread: one float4 (half of an 8-col group) -> 4 scalar stores at
// positions group*8 + 2*i + half  (same 32B sector, coalescing preserved).
__global__ void pack_tf32(const float4* __restrict__ in, int which, int cols4, int n4) {
    int id = blockIdx.x * blockDim.x + threadIdx.x;
    if (id >= n4) return;
    float* out = (which == 0) ? g_x  :
                 (which == 1) ? g_w1 :
                 (which == 2) ? g_w3 : g_w2;
    int c4   = id % cols4;
    size_t row = id / cols4;
    int half  = c4 & 1;
    int group = c4 >> 1;
    float4 v = in[id];
    float* dst = out + row * (size_t)(cols4 * 4) + group * 8 + half;
    dst[0] = rna_tf32(v.x);
    dst[2] = rna_tf32(v.y);
    dst[4] = rna_tf32(v.z);
    dst[6] = rna_tf32(v.w);
}

// ---------------- GEMM1: h = rna( silu(x@w1^T) * (x@w3^T) ) -------------------
// CTA 256M x 64N(each of w1,w3), BK=32, 256 thr (8 warps of 64x32 per weight)
// grid 1024 = e(8) x mt(8) x nt(16)
__global__ void __launch_bounds__(256, 1) moe_gemm1() {
    extern __shared__ float sm[];
    const int tid = threadIdx.x, lane = tid & 31, wid = tid >> 5;
    const int g = lane >> 2, t = lane & 3;
    const int bx = blockIdx.x;
    const int e = bx >> 7, mt = (bx >> 4) & 7, nt = bx & 15;
    const int m0 = e * 2048 + mt * 256, n0 = nt * 64;
    const float* A  = g_x  + (size_t)m0 * D_;
    const float* B1 = g_w1 + (size_t)(e * H_ + n0) * D_;
    const float* B3 = g_w3 + (size_t)(e * H_ + n0) * D_;
    const int KIT = D_ / 32;  // 64
    const int m_off = (wid & 3) * 64, n_off = (wid >> 2) * 32;

    float c1[4][4][4], c3[4][4][4];
    #pragma unroll
    for (int i = 0; i < 4; ++i)
        #pragma unroll
        for (int j = 0; j < 4; ++j)
            #pragma unroll
            for (int q = 0; q < 4; ++q) { c1[i][j][q] = 0.f; c3[i][j][q] = 0.f; }

    auto issue = [&](int s, int kt) {
        float* dst = sm + s * STG_FLOATS;
        const int koff = kt * 32;
        #pragma unroll
        for (int i = 0; i < 8; ++i) {             // A: 256 rows x 8 float4
            int idx = tid + 256 * i, r = idx >> 3, c = idx & 7;
            cp16(dst + r * RS + c * 4, A + (size_t)r * D_ + koff + c * 4);
        }
        float* d1 = dst + 10240;
        float* d3 = dst + 12800;
        #pragma unroll
        for (int i = 0; i < 2; ++i) {             // B1,B3: 64 rows x 8 float4
            int idx = tid + 256 * i, r = idx >> 3, c = idx & 7;
            cp16(d1 + r * RS + c * 4, B1 + (size_t)r * D_ + koff + c * 4);
            cp16(d3 + r * RS + c * 4, B3 + (size_t)r * D_ + koff + c * 4);
        }
        asm volatile("cp.async.commit_group;" ::: "memory");
    };

    issue(0, 0);
    for (int kt = 0; kt < KIT; ++kt) {
        int cur = kt & 1;
        if (kt + 1 < KIT) {
            issue(cur ^ 1, kt + 1);
            asm volatile("cp.async.wait_group 1;" ::: "memory");
        } else {
            asm volatile("cp.async.wait_group 0;" ::: "memory");
        }
        __syncthreads();
        const float* As  = sm + cur * STG_FLOATS;
        const float* B1s = As + 10240;
        const float* B3s = As + 12800;
        #pragma unroll
        for (int kk = 0; kk < 4; ++kk) {
            const int kb = kk * 8 + 2 * t;        // permuted pair offset
            uint32_t a[4][4], b1f[4][2], b3f[4][2];
            #pragma unroll
            for (int mi = 0; mi < 4; ++mi) {
                const float2 lo = *(const float2*)(As + (m_off + 16 * mi + g) * RS + kb);
                const float2 hi = *(const float2*)(As + (m_off + 16 * mi + g + 8) * RS + kb);
                a[mi][0] = __float_as_uint(lo.x); a[mi][2] = __float_as_uint(lo.y);
                a[mi][1] = __float_as_uint(hi.x); a[mi][3] = __float_as_uint(hi.y);
            }
            #pragma unroll
            for (int nj = 0; nj < 4; ++nj) {
                const float2 p = *(const float2*)(B1s + (n_off + 8 * nj + g) * RS + kb);
                b1f[nj][0] = __float_as_uint(p.x); b1f[nj][1] = __float_as_uint(p.y);
                const float2 q = *(const float2*)(B3s + (n_off + 8 * nj + g) * RS + kb);
                b3f[nj][0] = __float_as_uint(q.x); b3f[nj][1] = __float_as_uint(q.y);
            }
            #pragma unroll
            for (int mi = 0; mi < 4; ++mi)
                #pragma unroll
                for (int nj = 0; nj < 4; ++nj) {
                    mma_tf32(c1[mi][nj], a[mi], b1f[nj]);
                    mma_tf32(c3[mi][nj], a[mi], b3f[nj]);
                }
        }
        __syncthreads();
    }

    // epilogue: h = rna(silu(c1)*c3), written in PERMUTED layout for GEMM2.
    // logical cols 2t,2t+1 -> positions p0, p0+2 with p0 = (t<2) ? 4t : 4t-7
    const int p0 = (t < 2) ? 4 * t : 4 * t - 7;
    #pragma unroll
    for (int mi = 0; mi < 4; ++mi)
        #pragma unroll
        for (int nj = 0; nj < 4; ++nj) {
            int r0 = m0 + m_off + 16 * mi + g;
            float* db = g_h + (size_t)r0 * H_ + (n0 + n_off + 8 * nj);
            db[p0]     = rna_tf32(silu(c1[mi][nj][0]) * c3[mi][nj][0]);
            db[p0 + 2] = rna_tf32(silu(c1[mi][nj][1]) * c3[mi][nj][1]);
            float* dc = db + (size_t)8 * H_;
            dc[p0]     = rna_tf32(silu(c1[mi][nj][2]) * c3[mi][nj][2]);
            dc[p0 + 2] = rna_tf32(silu(c1[mi][nj][3]) * c3[mi][nj][3]);
        }
}

// ---------------- GEMM2: out = h @ w2^T ---------------------------------------
// CTA 256M x 128N, BK=32, K=1024; 256 thr (8 warps of 64x64)
// grid 1024 = e(8) x mt(8) x nt(16)
__global__ void __launch_bounds__(256, 1) moe_gemm2(float* __restrict__ out) {
    extern __shared__ float sm[];
    const int tid = threadIdx.x, lane = tid & 31, wid = tid >> 5;
    const int g = lane >> 2, t = lane & 3;
    const int bx = blockIdx.x;
    const int e = bx >> 7, mt = (bx >> 4) & 7, nt = bx & 15;
    const int m0 = e * 2048 + mt * 256, n0 = nt * 128;
    const float* A = g_h  + (size_t)m0 * H_;
    const float* B = g_w2 + ((size_t)e * D_ + n0) * H_;
    const int KIT = H_ / 32;  // 32
    const int m_off = (wid & 3) * 64, n_off = (wid >> 2) * 64;

    float cc[4][8][4];
    #pragma unroll
    for (int i = 0; i < 4; ++i)
        #pragma unroll
        for (int j = 0; j < 8; ++j)
            #pragma unroll
            for (int q = 0; q < 4; ++q) cc[i][j][q] = 0.f;

    auto issue = [&](int s, int kt) {
        float* dst = sm + s * STG_FLOATS;
        const int koff = kt * 32;
        #pragma unroll
        for (int i = 0; i < 8; ++i) {             // A: 256 x 8 float4
            int idx = tid + 256 * i, r = idx >> 3, c = idx & 7;
            cp16(dst + r * RS + c * 4, A + (size_t)r * H_ + koff + c * 4);
        }
        float* db = dst + 10240;
        #pragma unroll
        for (int i = 0; i < 4; ++i) {             // B: 128 x 8 float4
            int idx = tid + 256 * i, r = idx >> 3, c = idx & 7;
            cp16(db + r * RS + c * 4, B + (size_t)r * H_ + koff + c * 4);
        }
        asm volatile("cp.async.commit_group;" ::: "memory");
    };

    issue(0, 0);
    for (int kt = 0; kt < KIT; ++kt) {
        int cur = kt & 1;
        if (kt + 1 < KIT) {
            issue(cur ^ 1, kt + 1);
            asm volatile("cp.async.wait_group 1;" ::: "memory");
        } else {
            asm volatile("cp.async.wait_group 0;" ::: "memory");
        }
        __syncthreads();
        const float* As = sm + cur * STG_FLOATS;
        const float* Bs = As + 10240;
        #pragma unroll
        for (int kk = 0; kk < 4; ++kk) {
            const int kb = kk * 8 + 2 * t;
            uint32_t a[4][4], bf[8][2];
            #pragma unroll
            for (int mi = 0; mi < 4; ++mi) {
                const float2 lo = *(const float2*)(As + (m_off + 16 * mi + g) * RS + kb);
                const float2 hi = *(const float2*)(As + (m_off + 16 * mi + g + 8) * RS + kb);
                a[mi][0] = __float_as_uint(lo.x); a[mi][2] = __float_as_uint(lo.y);
                a[mi][1] = __float_as_uint(hi.x); a[mi][3] = __float_as_uint(hi.y);
            }
            #pragma unroll
            for (int nj = 0; nj < 8; ++nj) {
                const float2 p = *(const float2*)(Bs + (n_off + 8 * nj + g) * RS + kb);
                bf[nj][0] = __float_as_uint(p.x); bf[nj][1] = __float_as_uint(p.y);
            }
            #pragma unroll
            for (int mi = 0; mi < 4; ++mi)
                #pragma unroll
                for (int nj = 0; nj < 8; ++nj)
                    mma_tf32(cc[mi][nj], a[mi], bf[nj]);
        }
        __syncthreads();
    }

    // epilogue: plain fp32 stores (final output, logical layout)
    #pragma unroll
    for (int mi = 0; mi < 4; ++mi)
        #pragma unroll
        for (int nj = 0; nj < 8; ++nj) {
            int r0 = m0 + m_off + 16 * mi + g;
            int col = n0 + n_off + 8 * nj + 2 * t;
            float2 v;
            v.x = cc[mi][nj][0]; v.y = cc[mi][nj][1];
            *(float2*)(out + (size_t)r0 * D_ + col) = v;
            v.x = cc[mi][nj][2]; v.y = cc[mi][nj][3];
            *(float2*)(out + (size_t)(r0 + 8) * D_ + col) = v;
        }
}

// ---------------- launch ----------------
extern "C" void kernel_launch(void* const* d_in, const int* in_sizes, int n_in,
                              void* d_out, int out_size) {
    const float4* x  = (const float4*)d_in[0];
    const float4* w1 = (const float4*)d_in[2];
    const float4* w2 = (const float4*)d_in[3];
    const float4* w3 = (const float4*)d_in[4];
    float* out = (float*)d_out;

    int T4 = (int)((size_t)T_ * D_ / 4);      // 8388608
    int W4 = (int)((size_t)E_ * H_ * D_ / 4); // 4194304

    pack_tf32<<<T4 / 256, 256>>>(x,  0, D_ / 4, T4);
    pack_tf32<<<W4 / 256, 256>>>(w1, 1, D_ / 4, W4);
    pack_tf32<<<W4 / 256, 256>>>(w3, 2, D_ / 4, W4);
    pack_tf32<<<W4 / 256, 256>>>(w2, 3, H_ / 4, W4);

    cudaFuncSetAttribute(moe_gemm1, cudaFuncAttributeMaxDynamicSharedMemorySize, SMEM_SZ);
    cudaFuncSetAttribute(moe_gemm2, cudaFuncAttributeMaxDynamicSharedMemorySize, SMEM_SZ);

    moe_gemm1<<<1024, 256, SMEM_SZ>>>();
    moe_gemm2<<<1024, 256, SMEM_SZ>>>(out);
}

// round 6
// speedup vs baseline: 2.3009x; 1.8705x over previous
#include <cuda_runtime.h>
#include <cuda_fp16.h>
#include <cstdint>

#define E_ 8
#define T_ 16384
#define D_ 2048
#define H_ 1024

// ---------------- scratch: fp16 operands, pair-permuted within 16-col K-groups
__device__ __align__(1024) __half g_x [T_ * (size_t)D_];
__device__ __align__(1024) __half g_w1[E_ * (size_t)H_ * D_];
__device__ __align__(1024) __half g_w3[E_ * (size_t)H_ * D_];
__device__ __align__(1024) __half g_w2[E_ * (size_t)D_ * H_];
__device__ __align__(1024) __half g_h [T_ * (size_t)H_];

// ---------------- helpers ----------------
__device__ __forceinline__ uint32_t smem_u32(const void* p) {
    uint32_t a;
    asm("{ .reg .u64 t; cvta.to.shared.u64 t, %1; cvt.u32.u64 %0, t; }" : "=r"(a) : "l"(p));
    return a;
}
__device__ __forceinline__ uint32_t f22h(float lo, float hi) {   // fp16x2 {lo,hi}
    uint32_t r;
    asm("cvt.rn.f16x2.f32 %0, %1, %2;" : "=r"(r) : "f"(hi), "f"(lo));
    return r;
}
__device__ __forceinline__ void cp16(__half* sdst, const __half* gsrc) {
    uint32_t s = smem_u32(sdst);
    asm volatile("cp.async.cg.shared.global [%0], [%1], 16;" :: "r"(s), "l"(gsrc) : "memory");
}
__device__ __forceinline__ void mma_f16(float* c, const uint32_t* a, const uint32_t* b) {
    asm volatile(
        "mma.sync.aligned.m16n8k16.row.col.f32.f16.f16.f32 "
        "{%0,%1,%2,%3}, {%4,%5,%6,%7}, {%8,%9}, {%0,%1,%2,%3};"
        : "+f"(c[0]), "+f"(c[1]), "+f"(c[2]), "+f"(c[3])
        : "r"(a[0]), "r"(a[1]), "r"(a[2]), "r"(a[3]), "r"(b[0]), "r"(b[1]));
}
__device__ __forceinline__ float silu(float a) { return a / (1.f + __expf(-a)); }

// SMEM row stride 80 halfs (160B): LDS.64 fragment banks = (8g+2t) mod 32,
// distinct within each 16-lane phase -> conflict-free.
#define RS 80
#define STG_HALFS 30720        // A 256*80 + B 128*80 (or 64*80*2)
#define SMEM_SZ (2 * STG_HALFS * 2)

// ---------------- pack: fp32 -> fp16, pair-permuted 16-col groups -------------
// group of 16 cols -> 8 fp16x2 pairs stored as [p0,p4,p1,p5,p2,p6,p3,p7]
__global__ void pack_all(const float4* __restrict__ x,  const float4* __restrict__ w1,
                         const float4* __restrict__ w2, const float4* __restrict__ w3) {
    const size_t GX = (size_t)T_ * D_ / 16;        // 2097152
    const size_t GW = (size_t)E_ * H_ * D_ / 16;   // 1048576 (each weight)
    size_t id = (size_t)blockIdx.x * 256 + threadIdx.x;
    const float4* src; __half* dst; size_t gid;
    if (id < GX)                { src = x;  dst = g_x;  gid = id; }
    else if (id < GX + GW)      { src = w1; dst = g_w1; gid = id - GX; }
    else if (id < GX + 2 * GW)  { src = w3; dst = g_w3; gid = id - GX - GW; }
    else if (id < GX + 3 * GW)  { src = w2; dst = g_w2; gid = id - GX - 2 * GW; }
    else return;
    float4 v0 = src[gid * 4 + 0], v1 = src[gid * 4 + 1];
    float4 v2 = src[gid * 4 + 2], v3 = src[gid * 4 + 3];
    uint4 o0, o1;
    o0.x = f22h(v0.x, v0.y);  // p0
    o0.y = f22h(v2.x, v2.y);  // p4
    o0.z = f22h(v0.z, v0.w);  // p1
    o0.w = f22h(v2.z, v2.w);  // p5
    o1.x = f22h(v1.x, v1.y);  // p2
    o1.y = f22h(v3.x, v3.y);  // p6
    o1.z = f22h(v1.z, v1.w);  // p3
    o1.w = f22h(v3.z, v3.w);  // p7
    ((uint4*)dst)[gid * 2]     = o0;
    ((uint4*)dst)[gid * 2 + 1] = o1;
}

// ---------------- GEMM1: h = fp16( silu(x@w1^T) * (x@w3^T) ) ------------------
// CTA 256M x 64N (each of w1,w3), BK=64; 256 thr, warp 64x32 per weight
// grid 1024 = e(8) x mt(8) x nt(16)
__global__ void __launch_bounds__(256, 1) moe_gemm1() {
    extern __shared__ __half sm[];
    const int tid = threadIdx.x, lane = tid & 31, wid = tid >> 5;
    const int g = lane >> 2, t = lane & 3;
    const int bx = blockIdx.x;
    const int e = bx >> 7, mt = (bx >> 4) & 7, nt = bx & 15;
    const int m0 = e * 2048 + mt * 256, n0 = nt * 64;
    const __half* A  = g_x  + (size_t)m0 * D_;
    const __half* B1 = g_w1 + (size_t)(e * H_ + n0) * D_;
    const __half* B3 = g_w3 + (size_t)(e * H_ + n0) * D_;
    const int KIT = D_ / 64;  // 32
    const int m_off = (wid & 3) * 64, n_off = (wid >> 2) * 32;

    float c1[4][4][4], c3[4][4][4];
    #pragma unroll
    for (int i = 0; i < 4; ++i)
        #pragma unroll
        for (int j = 0; j < 4; ++j)
            #pragma unroll
            for (int q = 0; q < 4; ++q) { c1[i][j][q] = 0.f; c3[i][j][q] = 0.f; }

    auto issue = [&](int s, int kt) {
        __half* dst = sm + s * STG_HALFS;
        const int koff = kt * 64;
        #pragma unroll
        for (int i = 0; i < 8; ++i) {             // A: 256 rows x 8 chunks(16B)
            int idx = tid + 256 * i, r = idx >> 3, c = idx & 7;
            cp16(dst + r * RS + c * 8, A + (size_t)r * D_ + koff + c * 8);
        }
        __half* d1 = dst + 20480;
        __half* d3 = dst + 25600;
        #pragma unroll
        for (int i = 0; i < 2; ++i) {             // B1,B3: 64 rows x 8 chunks
            int idx = tid + 256 * i, r = idx >> 3, c = idx & 7;
            cp16(d1 + r * RS + c * 8, B1 + (size_t)r * D_ + koff + c * 8);
            cp16(d3 + r * RS + c * 8, B3 + (size_t)r * D_ + koff + c * 8);
        }
        asm volatile("cp.async.commit_group;" ::: "memory");
    };

    issue(0, 0);
    for (int kt = 0; kt < KIT; ++kt) {
        int cur = kt & 1;
        if (kt + 1 < KIT) {
            issue(cur ^ 1, kt + 1);
            asm volatile("cp.async.wait_group 1;" ::: "memory");
        } else {
            asm volatile("cp.async.wait_group 0;" ::: "memory");
        }
        __syncthreads();
        const __half* As  = sm + cur * STG_HALFS;
        const __half* B1s = As + 20480;
        const __half* B3s = As + 25600;
        #pragma unroll
        for (int kk = 0; kk < 4; ++kk) {
            const int kb = kk * 16 + 4 * t;       // permuted pair offset (halfs)
            uint32_t a[4][4], b1f[4][2], b3f[4][2];
            #pragma unroll
            for (int mi = 0; mi < 4; ++mi) {
                uint2 lo = *(const uint2*)(As + (m_off + 16 * mi + g) * RS + kb);
                uint2 hi = *(const uint2*)(As + (m_off + 16 * mi + g + 8) * RS + kb);
                a[mi][0] = lo.x; a[mi][1] = hi.x; a[mi][2] = lo.y; a[mi][3] = hi.y;
            }
            #pragma unroll
            for (int nj = 0; nj < 4; ++nj) {
                uint2 p = *(const uint2*)(B1s + (n_off + 8 * nj + g) * RS + kb);
                b1f[nj][0] = p.x; b1f[nj][1] = p.y;
                uint2 q = *(const uint2*)(B3s + (n_off + 8 * nj + g) * RS + kb);
                b3f[nj][0] = q.x; b3f[nj][1] = q.y;
            }
            #pragma unroll
            for (int mi = 0; mi < 4; ++mi)
                #pragma unroll
                for (int nj = 0; nj < 4; ++nj) {
                    mma_f16(c1[mi][nj], a[mi], b1f[nj]);
                    mma_f16(c3[mi][nj], a[mi], b3f[nj]);
                }
        }
        __syncthreads();
    }

    // epilogue: h = fp16(silu(c1)*c3), stored PERMUTED for GEMM2.
    // col nb=n0+n_off+8nj(+2t): pair p=(nj&1)*4+t -> slot 2t+(nj&1)
    #pragma unroll
    for (int mi = 0; mi < 4; ++mi)
        #pragma unroll
        for (int nj = 0; nj < 4; ++nj) {
            int r0 = m0 + m_off + 16 * mi + g;
            int nb = n0 + n_off + 8 * nj;
            size_t off = (size_t)(nb - 8 * (nj & 1)) + 4 * t + 2 * (nj & 1);
            uint32_t v0 = f22h(silu(c1[mi][nj][0]) * c3[mi][nj][0],
                               silu(c1[mi][nj][1]) * c3[mi][nj][1]);
            uint32_t v1 = f22h(silu(c1[mi][nj][2]) * c3[mi][nj][2],
                               silu(c1[mi][nj][3]) * c3[mi][nj][3]);
            *(uint32_t*)(g_h + (size_t)r0 * H_ + off)       = v0;
            *(uint32_t*)(g_h + (size_t)(r0 + 8) * H_ + off) = v1;
        }
}

// ---------------- GEMM2: out = h @ w2^T ---------------------------------------
// CTA 256M x 128N, BK=64, K=1024; 256 thr, warp 64x64
// grid 1024 = e(8) x mt(8) x nt(16)
__global__ void __launch_bounds__(256, 1) moe_gemm2(float* __restrict__ out) {
    extern __shared__ __half sm[];
    const int tid = threadIdx.x, lane = tid & 31, wid = tid >> 5;
    const int g = lane >> 2, t = lane & 3;
    const int bx = blockIdx.x;
    const int e = bx >> 7, mt = (bx >> 4) & 7, nt = bx & 15;
    const int m0 = e * 2048 + mt * 256, n0 = nt * 128;
    const __half* A = g_h  + (size_t)m0 * H_;
    const __half* B = g_w2 + ((size_t)e * D_ + n0) * H_;
    const int KIT = H_ / 64;  // 16
    const int m_off = (wid & 3) * 64, n_off = (wid >> 2) * 64;

    float cc[4][8][4];
    #pragma unroll
    for (int i = 0; i < 4; ++i)
        #pragma unroll
        for (int j = 0; j < 8; ++j)
            #pragma unroll
            for (int q = 0; q < 4; ++q) cc[i][j][q] = 0.f;

    auto issue = [&](int s, int kt) {
        __half* dst = sm + s * STG_HALFS;
        const int koff = kt * 64;
        #pragma unroll
        for (int i = 0; i < 8; ++i) {             // A: 256 x 8 chunks
            int idx = tid + 256 * i, r = idx >> 3, c = idx & 7;
            cp16(dst + r * RS + c * 8, A + (size_t)r * H_ + koff + c * 8);
        }
        __half* db = dst + 20480;
        #pragma unroll
        for (int i = 0; i < 4; ++i) {             // B: 128 x 8 chunks
            int idx = tid + 256 * i, r = idx >> 3, c = idx & 7;
            cp16(db + r * RS + c * 8, B + (size_t)r * H_ + koff + c * 8);
        }
        asm volatile("cp.async.commit_group;" ::: "memory");
    };

    issue(0, 0);
    for (int kt = 0; kt < KIT; ++kt) {
        int cur = kt & 1;
        if (kt + 1 < KIT) {
            issue(cur ^ 1, kt + 1);
            asm volatile("cp.async.wait_group 1;" ::: "memory");
        } else {
            asm volatile("cp.async.wait_group 0;" ::: "memory");
        }
        __syncthreads();
        const __half* As = sm + cur * STG_HALFS;
        const __half* Bs = As + 20480;
        #pragma unroll
        for (int kk = 0; kk < 4; ++kk) {
            const int kb = kk * 16 + 4 * t;
            uint32_t a[4][4], bf[8][2];
            #pragma unroll
            for (int mi = 0; mi < 4; ++mi) {
                uint2 lo = *(const uint2*)(As + (m_off + 16 * mi + g) * RS + kb);
                uint2 hi = *(const uint2*)(As + (m_off + 16 * mi + g + 8) * RS + kb);
                a[mi][0] = lo.x; a[mi][1] = hi.x; a[mi][2] = lo.y; a[mi][3] = hi.y;
            }
            #pragma unroll
            for (int nj = 0; nj < 8; ++nj) {
                uint2 p = *(const uint2*)(Bs + (n_off + 8 * nj + g) * RS + kb);
                bf[nj][0] = p.x; bf[nj][1] = p.y;
            }
            #pragma unroll
            for (int mi = 0; mi < 4; ++mi)
                #pragma unroll
                for (int nj = 0; nj < 8; ++nj)
                    mma_f16(cc[mi][nj], a[mi], bf[nj]);
        }
        __syncthreads();
    }

    #pragma unroll
    for (int mi = 0; mi < 4; ++mi)
        #pragma unroll
        for (int nj = 0; nj < 8; ++nj) {
            int r0 = m0 + m_off + 16 * mi + g;
            int col = n0 + n_off + 8 * nj + 2 * t;
            float2 v;
            v.x = cc[mi][nj][0]; v.y = cc[mi][nj][1];
            *(float2*)(out + (size_t)r0 * D_ + col) = v;
            v.x = cc[mi][nj][2]; v.y = cc[mi][nj][3];
            *(float2*)(out + (size_t)(r0 + 8) * D_ + col) = v;
        }
}

// ---------------- launch ----------------
extern "C" void kernel_launch(void* const* d_in, const int* in_sizes, int n_in,
                              void* d_out, int out_size) {
    const float4* x  = (const float4*)d_in[0];
    const float4* w1 = (const float4*)d_in[2];
    const float4* w2 = (const float4*)d_in[3];
    const float4* w3 = (const float4*)d_in[4];
    float* out = (float*)d_out;

    const size_t GX = (size_t)T_ * D_ / 16;
    const size_t GW = (size_t)E_ * H_ * D_ / 16;
    int nblk = (int)((GX + 3 * GW + 255) / 256);   // 20480

    pack_all<<<nblk, 256>>>(x, w1, w2, w3);

    cudaFuncSetAttribute(moe_gemm1, cudaFuncAttributeMaxDynamicSharedMemorySize, SMEM_SZ);
    cudaFuncSetAttribute(moe_gemm2, cudaFuncAttributeMaxDynamicSharedMemorySize, SMEM_SZ);

    moe_gemm1<<<1024, 256, SMEM_SZ>>>();
    moe_gemm2<<<1024, 256, SMEM_SZ>>>(out);
}

// round 7
// speedup vs baseline: 2.5740x; 1.1187x over previous
#include <cuda_runtime.h>
#include <cuda_fp16.h>
#include <cstdint>

#define E_ 8
#define T_ 16384
#define D_ 2048
#define H_ 1024

// ---------------- scratch: fp16 operands, plain row-major ---------------------
__device__ __align__(1024) __half g_x [T_ * (size_t)D_];
__device__ __align__(1024) __half g_w1[E_ * (size_t)H_ * D_];
__device__ __align__(1024) __half g_w3[E_ * (size_t)H_ * D_];
__device__ __align__(1024) __half g_w2[E_ * (size_t)D_ * H_];
__device__ __align__(1024) __half g_h [T_ * (size_t)H_];

// ---------------- helpers ----------------
__device__ __forceinline__ uint32_t smem_u32(const void* p) {
    uint32_t a;
    asm("{ .reg .u64 t; cvta.to.shared.u64 t, %1; cvt.u32.u64 %0, t; }" : "=r"(a) : "l"(p));
    return a;
}
__device__ __forceinline__ uint32_t f22h(float lo, float hi) {   // fp16x2 {lo,hi}
    uint32_t r;
    asm("cvt.rn.f16x2.f32 %0, %1, %2;" : "=r"(r) : "f"(hi), "f"(lo));
    return r;
}
__device__ __forceinline__ void cp16(__half* sdst, const __half* gsrc) {
    uint32_t s = smem_u32(sdst);
    asm volatile("cp.async.cg.shared.global [%0], [%1], 16;" :: "r"(s), "l"(gsrc) : "memory");
}
__device__ __forceinline__ void ldm_x4(uint32_t& r0, uint32_t& r1, uint32_t& r2, uint32_t& r3,
                                       uint32_t addr) {
    asm volatile("ldmatrix.sync.aligned.m8n8.x4.shared.b16 {%0,%1,%2,%3}, [%4];"
                 : "=r"(r0), "=r"(r1), "=r"(r2), "=r"(r3) : "r"(addr));
}
__device__ __forceinline__ void mma_f16(float* c, const uint32_t* a, const uint32_t* b) {
    asm volatile(
        "mma.sync.aligned.m16n8k16.row.col.f32.f16.f16.f32 "
        "{%0,%1,%2,%3}, {%4,%5,%6,%7}, {%8,%9}, {%0,%1,%2,%3};"
        : "+f"(c[0]), "+f"(c[1]), "+f"(c[2]), "+f"(c[3])
        : "r"(a[0]), "r"(a[1]), "r"(a[2]), "r"(a[3]), "r"(b[0]), "r"(b[1]));
}
__device__ __forceinline__ float silu(float a) { return a / (1.f + __expf(-a)); }

// Tiles: rows of 64 halfs (128B = 8 chunks of 16B), XOR swizzle chunk ^= row&7.
// cp.async writes and all ldmatrix quads are bank-conflict-free.
#define STG_BYTES 49152          // A 32KB + B 16KB (or 8KB+8KB)
#define NSTG 4
#define SMEM_SZ (NSTG * STG_BYTES)   // 192 KB

// ---------------- pack: fp32 -> fp16(rn), plain layout ------------------------
__global__ void pack_all(const float4* __restrict__ x,  const float4* __restrict__ w1,
                         const float4* __restrict__ w2, const float4* __restrict__ w3) {
    const size_t GX = (size_t)T_ * D_ / 8;        // 8 floats per thread
    const size_t GW = (size_t)E_ * H_ * D_ / 8;
    size_t id = (size_t)blockIdx.x * 256 + threadIdx.x;
    const float4* src; __half* dst; size_t gid;
    if (id < GX)               { src = x;  dst = g_x;  gid = id; }
    else if (id < GX + GW)     { src = w1; dst = g_w1; gid = id - GX; }
    else if (id < GX + 2 * GW) { src = w3; dst = g_w3; gid = id - GX - GW; }
    else if (id < GX + 3 * GW) { src = w2; dst = g_w2; gid = id - GX - 2 * GW; }
    else return;
    float4 v0 = src[gid * 2], v1 = src[gid * 2 + 1];
    uint4 o;
    o.x = f22h(v0.x, v0.y);
    o.y = f22h(v0.z, v0.w);
    o.z = f22h(v1.x, v1.y);
    o.w = f22h(v1.z, v1.w);
    ((uint4*)dst)[gid] = o;
}

// ---------------- GEMM1: h = fp16( silu(x@w1^T) * (x@w3^T) ) ------------------
// CTA 256M x 64N (each of w1,w3), BK=64; 256 thr, warp 64x32 per weight
// grid 1024 = e(8) x mt(8) x nt(16); stage: A 32KB | B1 8KB | B3 8KB
__global__ void __launch_bounds__(256, 1) moe_gemm1() {
    extern __shared__ __half sm[];
    const uint32_t sb = smem_u32(sm);
    const int tid = threadIdx.x, lane = tid & 31, wid = tid >> 5;
    const int g = lane >> 2, t = lane & 3, s7 = lane & 7;
    const int bx = blockIdx.x;
    const int e = bx >> 7, mt = (bx >> 4) & 7, nt = bx & 15;
    const int m0 = e * 2048 + mt * 256, n0 = nt * 64;
    const __half* A  = g_x  + (size_t)m0 * D_;
    const __half* B1 = g_w1 + (size_t)(e * H_ + n0) * D_;
    const __half* B3 = g_w3 + (size_t)(e * H_ + n0) * D_;
    const int KIT = D_ / 64;  // 32
    const int m_off = (wid & 3) * 64, n_off = (wid >> 2) * 32;

    // per-lane ldmatrix base addresses (stage 0)
    uint32_t aA[4], bA[4];
    #pragma unroll
    for (int kk = 0; kk < 4; ++kk) {
        aA[kk] = sb + (uint32_t)(m_off + (lane & 15)) * 128u
                    + 16u * ((((lane >> 4) | (kk << 1)) ^ s7));
        bA[kk] = sb + 32768u + (uint32_t)(n_off + 8 * (lane >> 4) + s7) * 128u
                    + 16u * (((((lane >> 3) & 1) | (kk << 1)) ^ s7));
    }

    float c1[4][4][4], c3[4][4][4];
    #pragma unroll
    for (int i = 0; i < 4; ++i)
        #pragma unroll
        for (int j = 0; j < 4; ++j)
            #pragma unroll
            for (int q = 0; q < 4; ++q) { c1[i][j][q] = 0.f; c3[i][j][q] = 0.f; }

    auto issue = [&](int s, int kt) {
        __half* dst = sm + (size_t)s * (STG_BYTES / 2);
        const int koff = kt * 64;
        #pragma unroll
        for (int i = 0; i < 8; ++i) {             // A: 256 rows x 8 chunks
            int idx = tid + 256 * i, r = idx >> 3, c = idx & 7;
            cp16(dst + r * 64 + ((c ^ (r & 7)) << 3), A + (size_t)r * D_ + koff + c * 8);
        }
        __half* d1 = dst + 16384;                 // halfs offset: 32KB
        __half* d3 = dst + 20480;
        #pragma unroll
        for (int i = 0; i < 2; ++i) {             // B1,B3: 64 rows x 8 chunks
            int idx = tid + 256 * i, r = idx >> 3, c = idx & 7;
            cp16(d1 + r * 64 + ((c ^ (r & 7)) << 3), B1 + (size_t)r * D_ + koff + c * 8);
            cp16(d3 + r * 64 + ((c ^ (r & 7)) << 3), B3 + (size_t)r * D_ + koff + c * 8);
        }
        asm volatile("cp.async.commit_group;" ::: "memory");
    };

    issue(0, 0); issue(1, 1);
    for (int kt = 0; kt < KIT; ++kt) {
        if (kt + 2 < KIT) {
            issue((kt + 2) & 3, kt + 2);
            asm volatile("cp.async.wait_group 2;" ::: "memory");
        } else if (kt + 1 < KIT) {
            asm volatile("cp.async.wait_group 1;" ::: "memory");
        } else {
            asm volatile("cp.async.wait_group 0;" ::: "memory");
        }
        __syncthreads();
        const uint32_t soff = (uint32_t)(kt & 3) * STG_BYTES;
        #pragma unroll
        for (int kk = 0; kk < 4; ++kk) {
            uint32_t a[4][4], b1f[4][2], b3f[4][2];
            #pragma unroll
            for (int mi = 0; mi < 4; ++mi)
                ldm_x4(a[mi][0], a[mi][1], a[mi][2], a[mi][3],
                       aA[kk] + soff + mi * 2048u);
            #pragma unroll
            for (int j = 0; j < 2; ++j) {
                ldm_x4(b1f[2*j][0], b1f[2*j][1], b1f[2*j+1][0], b1f[2*j+1][1],
                       bA[kk] + soff + j * 2048u);
                ldm_x4(b3f[2*j][0], b3f[2*j][1], b3f[2*j+1][0], b3f[2*j+1][1],
                       bA[kk] + soff + 8192u + j * 2048u);
            }
            #pragma unroll
            for (int mi = 0; mi < 4; ++mi)
                #pragma unroll
                for (int nj = 0; nj < 4; ++nj) {
                    mma_f16(c1[mi][nj], a[mi], b1f[nj]);
                    mma_f16(c3[mi][nj], a[mi], b3f[nj]);
                }
        }
        __syncthreads();
    }

    // epilogue: h = fp16(silu(c1)*c3), plain row-major
    #pragma unroll
    for (int mi = 0; mi < 4; ++mi)
        #pragma unroll
        for (int nj = 0; nj < 4; ++nj) {
            int r0 = m0 + m_off + 16 * mi + g;
            int col = n0 + n_off + 8 * nj + 2 * t;
            uint32_t v0 = f22h(silu(c1[mi][nj][0]) * c3[mi][nj][0],
                               silu(c1[mi][nj][1]) * c3[mi][nj][1]);
            uint32_t v1 = f22h(silu(c1[mi][nj][2]) * c3[mi][nj][2],
                               silu(c1[mi][nj][3]) * c3[mi][nj][3]);
            *(uint32_t*)(g_h + (size_t)r0 * H_ + col)       = v0;
            *(uint32_t*)(g_h + (size_t)(r0 + 8) * H_ + col) = v1;
        }
}

// ---------------- GEMM2: out = h @ w2^T ---------------------------------------
// CTA 256M x 128N, BK=64, K=1024; 256 thr, warp 64x64
// grid 1024 = e(8) x mt(8) x nt(16); stage: A 32KB | B 16KB
__global__ void __launch_bounds__(256, 1) moe_gemm2(float* __restrict__ out) {
    extern __shared__ __half sm[];
    const uint32_t sb = smem_u32(sm);
    const int tid = threadIdx.x, lane = tid & 31, wid = tid >> 5;
    const int g = lane >> 2, t = lane & 3, s7 = lane & 7;
    const int bx = blockIdx.x;
    const int e = bx >> 7, mt = (bx >> 4) & 7, nt = bx & 15;
    const int m0 = e * 2048 + mt * 256, n0 = nt * 128;
    const __half* A = g_h  + (size_t)m0 * H_;
    const __half* B = g_w2 + ((size_t)e * D_ + n0) * H_;
    const int KIT = H_ / 64;  // 16
    const int m_off = (wid & 3) * 64, n_off = (wid >> 2) * 64;

    uint32_t aA[4], bA[4];
    #pragma unroll
    for (int kk = 0; kk < 4; ++kk) {
        aA[kk] = sb + (uint32_t)(m_off + (lane & 15)) * 128u
                    + 16u * ((((lane >> 4) | (kk << 1)) ^ s7));
        bA[kk] = sb + 32768u + (uint32_t)(n_off + 8 * (lane >> 4) + s7) * 128u
                    + 16u * (((((lane >> 3) & 1) | (kk << 1)) ^ s7));
    }

    float cc[4][8][4];
    #pragma unroll
    for (int i = 0; i < 4; ++i)
        #pragma unroll
        for (int j = 0; j < 8; ++j)
            #pragma unroll
            for (int q = 0; q < 4; ++q) cc[i][j][q] = 0.f;

    auto issue = [&](int s, int kt) {
        __half* dst = sm + (size_t)s * (STG_BYTES / 2);
        const int koff = kt * 64;
        #pragma unroll
        for (int i = 0; i < 8; ++i) {             // A: 256 x 8 chunks
            int idx = tid + 256 * i, r = idx >> 3, c = idx & 7;
            cp16(dst + r * 64 + ((c ^ (r & 7)) << 3), A + (size_t)r * H_ + koff + c * 8);
        }
        __half* db = dst + 16384;
        #pragma unroll
        for (int i = 0; i < 4; ++i) {             // B: 128 x 8 chunks
            int idx = tid + 256 * i, r = idx >> 3, c = idx & 7;
            cp16(db + r * 64 + ((c ^ (r & 7)) << 3), B + (size_t)r * H_ + koff + c * 8);
        }
        asm volatile("cp.async.commit_group;" ::: "memory");
    };

    issue(0, 0); issue(1, 1);
    for (int kt = 0; kt < KIT; ++kt) {
        if (kt + 2 < KIT) {
            issue((kt + 2) & 3, kt + 2);
            asm volatile("cp.async.wait_group 2;" ::: "memory");
        } else if (kt + 1 < KIT) {
            asm volatile("cp.async.wait_group 1;" ::: "memory");
        } else {
            asm volatile("cp.async.wait_group 0;" ::: "memory");
        }
        __syncthreads();
        const uint32_t soff = (uint32_t)(kt & 3) * STG_BYTES;
        #pragma unroll
        for (int kk = 0; kk < 4; ++kk) {
            uint32_t a[4][4], bf[8][2];
            #pragma unroll
            for (int mi = 0; mi < 4; ++mi)
                ldm_x4(a[mi][0], a[mi][1], a[mi][2], a[mi][3],
                       aA[kk] + soff + mi * 2048u);
            #pragma unroll
            for (int j = 0; j < 4; ++j)
                ldm_x4(bf[2*j][0], bf[2*j][1], bf[2*j+1][0], bf[2*j+1][1],
                       bA[kk] + soff + j * 2048u);
            #pragma unroll
            for (int mi = 0; mi < 4; ++mi)
                #pragma unroll
                for (int nj = 0; nj < 8; ++nj)
                    mma_f16(cc[mi][nj], a[mi], bf[nj]);
        }
        __syncthreads();
    }

    #pragma unroll
    for (int mi = 0; mi < 4; ++mi)
        #pragma unroll
        for (int nj = 0; nj < 8; ++nj) {
            int r0 = m0 + m_off + 16 * mi + g;
            int col = n0 + n_off + 8 * nj + 2 * t;
            float2 v;
            v.x = cc[mi][nj][0]; v.y = cc[mi][nj][1];
            *(float2*)(out + (size_t)r0 * D_ + col) = v;
            v.x = cc[mi][nj][2]; v.y = cc[mi][nj][3];
            *(float2*)(out + (size_t)(r0 + 8) * D_ + col) = v;
        }
}

// ---------------- launch ----------------
extern "C" void kernel_launch(void* const* d_in, const int* in_sizes, int n_in,
                              void* d_out, int out_size) {
    const float4* x  = (const float4*)d_in[0];
    const float4* w1 = (const float4*)d_in[2];
    const float4* w2 = (const float4*)d_in[3];
    const float4* w3 = (const float4*)d_in[4];
    float* out = (float*)d_out;

    const size_t GX = (size_t)T_ * D_ / 8;
    const size_t GW = (size_t)E_ * H_ * D_ / 8;
    int nblk = (int)((GX + 3 * GW + 255) / 256);   // 40960

    pack_all<<<nblk, 256>>>(x, w1, w2, w3);

    cudaFuncSetAttribute(moe_gemm1, cudaFuncAttributeMaxDynamicSharedMemorySize, SMEM_SZ);
    cudaFuncSetAttribute(moe_gemm2, cudaFuncAttributeMaxDynamicSharedMemorySize, SMEM_SZ);

    moe_gemm1<<<1024, 256, SMEM_SZ>>>();
    moe_gemm2<<<1024, 256, SMEM_SZ>>>(out);
}

// round 8
// speedup vs baseline: 2.8132x; 1.0929x over previous
#include <cuda_runtime.h>
#include <cuda_fp16.h>
#include <cstdint>

#define E_ 8
#define T_ 16384
#define D_ 2048
#define H_ 1024

// ---------------- scratch: fp16 operands, plain row-major ---------------------
__device__ __align__(1024) __half g_x [T_ * (size_t)D_];
__device__ __align__(1024) __half g_w1[E_ * (size_t)H_ * D_];
__device__ __align__(1024) __half g_w3[E_ * (size_t)H_ * D_];
__device__ __align__(1024) __half g_w2[E_ * (size_t)D_ * H_];
__device__ __align__(1024) __half g_h [T_ * (size_t)H_];

// ---------------- helpers ----------------
__device__ __forceinline__ uint32_t smem_u32(const void* p) {
    uint32_t a;
    asm("{ .reg .u64 t; cvta.to.shared.u64 t, %1; cvt.u32.u64 %0, t; }" : "=r"(a) : "l"(p));
    return a;
}
__device__ __forceinline__ uint32_t f22h(float lo, float hi) {   // fp16x2 {lo,hi}
    uint32_t r;
    asm("cvt.rn.f16x2.f32 %0, %1, %2;" : "=r"(r) : "f"(hi), "f"(lo));
    return r;
}
__device__ __forceinline__ void cp16(__half* sdst, const __half* gsrc) {
    uint32_t s = smem_u32(sdst);
    asm volatile("cp.async.cg.shared.global [%0], [%1], 16;" :: "r"(s), "l"(gsrc) : "memory");
}
__device__ __forceinline__ void ldm_x4(uint32_t& r0, uint32_t& r1, uint32_t& r2, uint32_t& r3,
                                       uint32_t addr) {
    asm volatile("ldmatrix.sync.aligned.m8n8.x4.shared.b16 {%0,%1,%2,%3}, [%4];"
                 : "=r"(r0), "=r"(r1), "=r"(r2), "=r"(r3) : "r"(addr));
}
__device__ __forceinline__ void mma_f16(float* c, const uint32_t* a, const uint32_t* b) {
    asm volatile(
        "mma.sync.aligned.m16n8k16.row.col.f32.f16.f16.f32 "
        "{%0,%1,%2,%3}, {%4,%5,%6,%7}, {%8,%9}, {%0,%1,%2,%3};"
        : "+f"(c[0]), "+f"(c[1]), "+f"(c[2]), "+f"(c[3])
        : "r"(a[0]), "r"(a[1]), "r"(a[2]), "r"(a[3]), "r"(b[0]), "r"(b[1]));
}
__device__ __forceinline__ float silu(float a) { return a / (1.f + __expf(-a)); }

// Tiles: rows of 64 halfs (128B = 8 chunks of 16B), XOR swizzle chunk ^= row&7.
#define STG_BYTES 32768          // A 16KB + B 16KB (or 16 + 8 + 8)
#define NSTG 3
#define SMEM_SZ (NSTG * STG_BYTES)   // 96 KB -> 2 CTAs/SM

// ---------------- pack: fp32 -> fp16(rn), plain layout ------------------------
__global__ void pack_all(const float4* __restrict__ x,  const float4* __restrict__ w1,
                         const float4* __restrict__ w2, const float4* __restrict__ w3) {
    const size_t GX = (size_t)T_ * D_ / 8;        // 8 floats per thread
    const size_t GW = (size_t)E_ * H_ * D_ / 8;
    size_t id = (size_t)blockIdx.x * 256 + threadIdx.x;
    const float4* src; __half* dst; size_t gid;
    if (id < GX)               { src = x;  dst = g_x;  gid = id; }
    else if (id < GX + GW)     { src = w1; dst = g_w1; gid = id - GX; }
    else if (id < GX + 2 * GW) { src = w3; dst = g_w3; gid = id - GX - GW; }
    else if (id < GX + 3 * GW) { src = w2; dst = g_w2; gid = id - GX - 2 * GW; }
    else return;
    float4 v0 = src[gid * 2], v1 = src[gid * 2 + 1];
    uint4 o;
    o.x = f22h(v0.x, v0.y);
    o.y = f22h(v0.z, v0.w);
    o.z = f22h(v1.x, v1.y);
    o.w = f22h(v1.z, v1.w);
    ((uint4*)dst)[gid] = o;
}

// ---------------- GEMM1: h = fp16( silu(x@w1^T) * (x@w3^T) ) ------------------
// CTA 128M x 64N (each of w1,w3), BK=64; 128 thr (4 warps, 64x32 per weight)
// grid 2048 = e(8) x mt(16) x nt(16); stage: A 16KB | B1 8KB | B3 8KB
__global__ void __launch_bounds__(128, 2) moe_gemm1() {
    extern __shared__ __half sm[];
    const uint32_t sb = smem_u32(sm);
    const int tid = threadIdx.x, lane = tid & 31, wid = tid >> 5;
    const int g = lane >> 2, t = lane & 3, s7 = lane & 7;
    const int bx = blockIdx.x;
    const int e = bx >> 8, mt = (bx >> 4) & 15, nt = bx & 15;
    const int m0 = e * 2048 + mt * 128, n0 = nt * 64;
    const __half* A  = g_x  + (size_t)m0 * D_;
    const __half* B1 = g_w1 + (size_t)(e * H_ + n0) * D_;
    const __half* B3 = g_w3 + (size_t)(e * H_ + n0) * D_;
    const int KIT = D_ / 64;  // 32
    const int m_off = (wid & 1) * 64, n_off = (wid >> 1) * 32;

    // per-lane ldmatrix base addresses (stage 0)
    uint32_t aA[4], bA[4];
    #pragma unroll
    for (int kk = 0; kk < 4; ++kk) {
        aA[kk] = sb + (uint32_t)(m_off + (lane & 15)) * 128u
                    + 16u * ((((lane >> 4) | (kk << 1)) ^ s7));
        bA[kk] = sb + 16384u + (uint32_t)(n_off + 8 * (lane >> 4) + s7) * 128u
                    + 16u * (((((lane >> 3) & 1) | (kk << 1)) ^ s7));
    }

    float c1[4][4][4], c3[4][4][4];
    #pragma unroll
    for (int i = 0; i < 4; ++i)
        #pragma unroll
        for (int j = 0; j < 4; ++j)
            #pragma unroll
            for (int q = 0; q < 4; ++q) { c1[i][j][q] = 0.f; c3[i][j][q] = 0.f; }

    auto issue = [&](int s, int kt) {
        __half* dst = sm + (size_t)s * (STG_BYTES / 2);
        const int koff = kt * 64;
        #pragma unroll
        for (int i = 0; i < 8; ++i) {             // A: 128 rows x 8 chunks
            int idx = tid + 128 * i, r = idx >> 3, c = idx & 7;
            cp16(dst + r * 64 + ((c ^ (r & 7)) << 3), A + (size_t)r * D_ + koff + c * 8);
        }
        __half* d1 = dst + 8192;                  // +16KB
        __half* d3 = dst + 12288;                 // +24KB
        #pragma unroll
        for (int i = 0; i < 4; ++i) {             // B1,B3: 64 rows x 8 chunks
            int idx = tid + 128 * i, r = idx >> 3, c = idx & 7;
            cp16(d1 + r * 64 + ((c ^ (r & 7)) << 3), B1 + (size_t)r * D_ + koff + c * 8);
            cp16(d3 + r * 64 + ((c ^ (r & 7)) << 3), B3 + (size_t)r * D_ + koff + c * 8);
        }
        asm volatile("cp.async.commit_group;" ::: "memory");
    };

    issue(0, 0); issue(1, 1);
    int cs = 0;
    for (int kt = 0; kt < KIT; ++kt) {
        if (kt + 1 < KIT) asm volatile("cp.async.wait_group 1;" ::: "memory");
        else              asm volatile("cp.async.wait_group 0;" ::: "memory");
        __syncthreads();
        if (kt + 2 < KIT) { int ns = cs + 2; if (ns >= 3) ns -= 3; issue(ns, kt + 2); }
        const uint32_t soff = (uint32_t)cs * STG_BYTES;
        #pragma unroll
        for (int kk = 0; kk < 4; ++kk) {
            uint32_t a[4][4], b1f[4][2], b3f[4][2];
            #pragma unroll
            for (int mi = 0; mi < 4; ++mi)
                ldm_x4(a[mi][0], a[mi][1], a[mi][2], a[mi][3],
                       aA[kk] + soff + mi * 2048u);
            #pragma unroll
            for (int j = 0; j < 2; ++j) {
                ldm_x4(b1f[2*j][0], b1f[2*j][1], b1f[2*j+1][0], b1f[2*j+1][1],
                       bA[kk] + soff + j * 2048u);
                ldm_x4(b3f[2*j][0], b3f[2*j][1], b3f[2*j+1][0], b3f[2*j+1][1],
                       bA[kk] + soff + 8192u + j * 2048u);
            }
            #pragma unroll
            for (int mi = 0; mi < 4; ++mi)
                #pragma unroll
                for (int nj = 0; nj < 4; ++nj) {
                    mma_f16(c1[mi][nj], a[mi], b1f[nj]);
                    mma_f16(c3[mi][nj], a[mi], b3f[nj]);
                }
        }
        if (++cs == 3) cs = 0;
    }

    // epilogue: h = fp16(silu(c1)*c3), plain row-major
    #pragma unroll
    for (int mi = 0; mi < 4; ++mi)
        #pragma unroll
        for (int nj = 0; nj < 4; ++nj) {
            int r0 = m0 + m_off + 16 * mi + g;
            int col = n0 + n_off + 8 * nj + 2 * t;
            uint32_t v0 = f22h(silu(c1[mi][nj][0]) * c3[mi][nj][0],
                               silu(c1[mi][nj][1]) * c3[mi][nj][1]);
            uint32_t v1 = f22h(silu(c1[mi][nj][2]) * c3[mi][nj][2],
                               silu(c1[mi][nj][3]) * c3[mi][nj][3]);
            *(uint32_t*)(g_h + (size_t)r0 * H_ + col)       = v0;
            *(uint32_t*)(g_h + (size_t)(r0 + 8) * H_ + col) = v1;
        }
}

// ---------------- GEMM2: out = h @ w2^T ---------------------------------------
// CTA 128M x 128N, BK=64, K=1024; 128 thr (4 warps, 64x64)
// grid 2048 = e(8) x mt(16) x nt(16); stage: A 16KB | B 16KB
__global__ void __launch_bounds__(128, 2) moe_gemm2(float* __restrict__ out) {
    extern __shared__ __half sm[];
    const uint32_t sb = smem_u32(sm);
    const int tid = threadIdx.x, lane = tid & 31, wid = tid >> 5;
    const int g = lane >> 2, t = lane & 3, s7 = lane & 7;
    const int bx = blockIdx.x;
    const int e = bx >> 8, mt = (bx >> 4) & 15, nt = bx & 15;
    const int m0 = e * 2048 + mt * 128, n0 = nt * 128;
    const __half* A = g_h  + (size_t)m0 * H_;
    const __half* B = g_w2 + ((size_t)e * D_ + n0) * H_;
    const int KIT = H_ / 64;  // 16
    const int m_off = (wid & 1) * 64, n_off = (wid >> 1) * 64;

    uint32_t aA[4], bA[4];
    #pragma unroll
    for (int kk = 0; kk < 4; ++kk) {
        aA[kk] = sb + (uint32_t)(m_off + (lane & 15)) * 128u
                    + 16u * ((((lane >> 4) | (kk << 1)) ^ s7));
        bA[kk] = sb + 16384u + (uint32_t)(n_off + 8 * (lane >> 4) + s7) * 128u
                    + 16u * (((((lane >> 3) & 1) | (kk << 1)) ^ s7));
    }

    float cc[4][8][4];
    #pragma unroll
    for (int i = 0; i < 4; ++i)
        #pragma unroll
        for (int j = 0; j < 8; ++j)
            #pragma unroll
            for (int q = 0; q < 4; ++q) cc[i][j][q] = 0.f;

    auto issue = [&](int s, int kt) {
        __half* dst = sm + (size_t)s * (STG_BYTES / 2);
        const int koff = kt * 64;
        #pragma unroll
        for (int i = 0; i < 8; ++i) {             // A: 128 x 8 chunks
            int idx = tid + 128 * i, r = idx >> 3, c = idx & 7;
            cp16(dst + r * 64 + ((c ^ (r & 7)) << 3), A + (size_t)r * H_ + koff + c * 8);
        }
        __half* db = dst + 8192;                  // +16KB
        #pragma unroll
        for (int i = 0; i < 8; ++i) {             // B: 128 x 8 chunks
            int idx = tid + 128 * i, r = idx >> 3, c = idx & 7;
            cp16(db + r * 64 + ((c ^ (r & 7)) << 3), B + (size_t)r * H_ + koff + c * 8);
        }
        asm volatile("cp.async.commit_group;" ::: "memory");
    };

    issue(0, 0); issue(1, 1);
    int cs = 0;
    for (int kt = 0; kt < KIT; ++kt) {
        if (kt + 1 < KIT) asm volatile("cp.async.wait_group 1;" ::: "memory");
        else              asm volatile("cp.async.wait_group 0;" ::: "memory");
        __syncthreads();
        if (kt + 2 < KIT) { int ns = cs + 2; if (ns >= 3) ns -= 3; issue(ns, kt + 2); }
        const uint32_t soff = (uint32_t)cs * STG_BYTES;
        #pragma unroll
        for (int kk = 0; kk < 4; ++kk) {
            uint32_t a[4][4], bf[8][2];
            #pragma unroll
            for (int mi = 0; mi < 4; ++mi)
                ldm_x4(a[mi][0], a[mi][1], a[mi][2], a[mi][3],
                       aA[kk] + soff + mi * 2048u);
            #pragma unroll
            for (int j = 0; j < 4; ++j)
                ldm_x4(bf[2*j][0], bf[2*j][1], bf[2*j+1][0], bf[2*j+1][1],
                       bA[kk] + soff + j * 2048u);
            #pragma unroll
            for (int mi = 0; mi < 4; ++mi)
                #pragma unroll
                for (int nj = 0; nj < 8; ++nj)
                    mma_f16(cc[mi][nj], a[mi], bf[nj]);
        }
        if (++cs == 3) cs = 0;
    }

    #pragma unroll
    for (int mi = 0; mi < 4; ++mi)
        #pragma unroll
        for (int nj = 0; nj < 8; ++nj) {
            int r0 = m0 + m_off + 16 * mi + g;
            int col = n0 + n_off + 8 * nj + 2 * t;
            float2 v;
            v.x = cc[mi][nj][0]; v.y = cc[mi][nj][1];
            *(float2*)(out + (size_t)r0 * D_ + col) = v;
            v.x = cc[mi][nj][2]; v.y = cc[mi][nj][3];
            *(float2*)(out + (size_t)(r0 + 8) * D_ + col) = v;
        }
}

// ---------------- launch ----------------
extern "C" void kernel_launch(void* const* d_in, const int* in_sizes, int n_in,
                              void* d_out, int out_size) {
    const float4* x  = (const float4*)d_in[0];
    const float4* w1 = (const float4*)d_in[2];
    const float4* w2 = (const float4*)d_in[3];
    const float4* w3 = (const float4*)d_in[4];
    float* out = (float*)d_out;

    const size_t GX = (size_t)T_ * D_ / 8;
    const size_t GW = (size_t)E_ * H_ * D_ / 8;
    int nblk = (int)((GX + 3 * GW + 255) / 256);   // 40960

    pack_all<<<nblk, 256>>>(x, w1, w2, w3);

    cudaFuncSetAttribute(moe_gemm1, cudaFuncAttributeMaxDynamicSharedMemorySize, SMEM_SZ);
    cudaFuncSetAttribute(moe_gemm2, cudaFuncAttributeMaxDynamicSharedMemorySize, SMEM_SZ);

    moe_gemm1<<<2048, 128, SMEM_SZ>>>();
    moe_gemm2<<<2048, 128, SMEM_SZ>>>(out);
}

// round 9
// speedup vs baseline: 2.8437x; 1.0108x over previous
#include <cuda_runtime.h>
#include <cuda_fp16.h>
#include <cstdint>

#define E_ 8
#define T_ 16384
#define D_ 2048
#define H_ 1024

// ---------------- scratch: fp16 operands, plain row-major ---------------------
__device__ __align__(1024) __half g_x [T_ * (size_t)D_];
__device__ __align__(1024) __half g_w1[E_ * (size_t)H_ * D_];
__device__ __align__(1024) __half g_w3[E_ * (size_t)H_ * D_];
__device__ __align__(1024) __half g_w2[E_ * (size_t)D_ * H_];
__device__ __align__(1024) __half g_h [T_ * (size_t)H_];

// ---------------- helpers ----------------
__device__ __forceinline__ uint32_t smem_u32(const void* p) {
    uint32_t a;
    asm("{ .reg .u64 t; cvta.to.shared.u64 t, %1; cvt.u32.u64 %0, t; }" : "=r"(a) : "l"(p));
    return a;
}
__device__ __forceinline__ uint32_t f22h(float lo, float hi) {   // fp16x2 {lo,hi}
    uint32_t r;
    asm("cvt.rn.f16x2.f32 %0, %1, %2;" : "=r"(r) : "f"(hi), "f"(lo));
    return r;
}
__device__ __forceinline__ void cp16(__half* sdst, const __half* gsrc) {
    uint32_t s = smem_u32(sdst);
    asm volatile("cp.async.cg.shared.global [%0], [%1], 16;" :: "r"(s), "l"(gsrc) : "memory");
}
__device__ __forceinline__ void ldm_x4(uint32_t& r0, uint32_t& r1, uint32_t& r2, uint32_t& r3,
                                       uint32_t addr) {
    asm volatile("ldmatrix.sync.aligned.m8n8.x4.shared.b16 {%0,%1,%2,%3}, [%4];"
                 : "=r"(r0), "=r"(r1), "=r"(r2), "=r"(r3) : "r"(addr));
}
__device__ __forceinline__ void mma_f16(float* c, const uint32_t* a, const uint32_t* b) {
    asm volatile(
        "mma.sync.aligned.m16n8k16.row.col.f32.f16.f16.f32 "
        "{%0,%1,%2,%3}, {%4,%5,%6,%7}, {%8,%9}, {%0,%1,%2,%3};"
        : "+f"(c[0]), "+f"(c[1]), "+f"(c[2]), "+f"(c[3])
        : "r"(a[0]), "r"(a[1]), "r"(a[2]), "r"(a[3]), "r"(b[0]), "r"(b[1]));
}
__device__ __forceinline__ float silu(float a) { return a / (1.f + __expf(-a)); }

// Tiles: rows of 64 halfs (128B = 8 chunks of 16B), XOR swizzle chunk ^= row&7.
#define STG_BYTES 32768          // A 16KB + B 16KB (or 16 + 8 + 8)
#define NSTG 3
#define SMEM_SZ (NSTG * STG_BYTES)   // 96 KB -> 2 CTAs/SM

// ---------------- pack x, w1, w3 (w2 is packed inside moe_gemm1) --------------
__global__ void pack_xw13(const float4* __restrict__ x, const float4* __restrict__ w1,
                          const float4* __restrict__ w3) {
    const size_t GX = (size_t)T_ * D_ / 8;        // 8 floats per thread
    const size_t GW = (size_t)E_ * H_ * D_ / 8;
    size_t id = (size_t)blockIdx.x * 256 + threadIdx.x;
    const float4* src; __half* dst; size_t gid;
    if (id < GX)               { src = x;  dst = g_x;  gid = id; }
    else if (id < GX + GW)     { src = w1; dst = g_w1; gid = id - GX; }
    else if (id < GX + 2 * GW) { src = w3; dst = g_w3; gid = id - GX - GW; }
    else return;
    float4 v0 = src[gid * 2], v1 = src[gid * 2 + 1];
    uint4 o;
    o.x = f22h(v0.x, v0.y);
    o.y = f22h(v0.z, v0.w);
    o.z = f22h(v1.x, v1.y);
    o.w = f22h(v1.z, v1.w);
    ((uint4*)dst)[gid] = o;
}

// ---------------- GEMM1 + fused w2 pack ---------------------------------------
// grid 2560: every 5th block packs w2 (512 blocks), rest are GEMM tiles (2048).
// GEMM: CTA 128M x 64N (each of w1,w3), BK=64; 128 thr (4 warps, 64x32/weight)
// stage: A 16KB | B1 8KB | B3 8KB
__global__ void __launch_bounds__(128, 2) moe_gemm1(const float4* __restrict__ w2src) {
    extern __shared__ __half sm[];
    const uint32_t sb = smem_u32(sm);
    const int tid = threadIdx.x, lane = tid & 31, wid = tid >> 5;
    const int g = lane >> 2, t = lane & 3, s7 = lane & 7;
    const int bxr = blockIdx.x;

    if ((bxr % 5) == 4) {                          // ---- w2 pack branch ----
        const size_t N4 = (size_t)E_ * D_ * H_ / 8;   // 2097152 (8 floats each)
        size_t pid = (size_t)(bxr / 5);               // 0..511
        for (size_t i = pid * 128 + tid; i < N4; i += 512 * 128) {
            float4 v0 = w2src[i * 2], v1 = w2src[i * 2 + 1];
            uint4 o;
            o.x = f22h(v0.x, v0.y);
            o.y = f22h(v0.z, v0.w);
            o.z = f22h(v1.x, v1.y);
            o.w = f22h(v1.z, v1.w);
            ((uint4*)g_w2)[i] = o;
        }
        return;
    }
    const int bx = bxr - bxr / 5;                  // 0..2047 gemm tile index

    const int e = bx >> 8, mt = (bx >> 4) & 15, nt = bx & 15;
    const int m0 = e * 2048 + mt * 128, n0 = nt * 64;
    const __half* A  = g_x  + (size_t)m0 * D_;
    const __half* B1 = g_w1 + (size_t)(e * H_ + n0) * D_;
    const __half* B3 = g_w3 + (size_t)(e * H_ + n0) * D_;
    const int KIT = D_ / 64;  // 32
    const int m_off = (wid & 1) * 64, n_off = (wid >> 1) * 32;

    uint32_t aA[4], bA[4];
    #pragma unroll
    for (int kk = 0; kk < 4; ++kk) {
        aA[kk] = sb + (uint32_t)(m_off + (lane & 15)) * 128u
                    + 16u * ((((lane >> 4) | (kk << 1)) ^ s7));
        bA[kk] = sb + 16384u + (uint32_t)(n_off + 8 * (lane >> 4) + s7) * 128u
                    + 16u * (((((lane >> 3) & 1) | (kk << 1)) ^ s7));
    }

    float c1[4][4][4], c3[4][4][4];
    #pragma unroll
    for (int i = 0; i < 4; ++i)
        #pragma unroll
        for (int j = 0; j < 4; ++j)
            #pragma unroll
            for (int q = 0; q < 4; ++q) { c1[i][j][q] = 0.f; c3[i][j][q] = 0.f; }

    auto issue = [&](int s, int kt) {
        __half* dst = sm + (size_t)s * (STG_BYTES / 2);
        const int koff = kt * 64;
        #pragma unroll
        for (int i = 0; i < 8; ++i) {             // A: 128 rows x 8 chunks
            int idx = tid + 128 * i, r = idx >> 3, c = idx & 7;
            cp16(dst + r * 64 + ((c ^ (r & 7)) << 3), A + (size_t)r * D_ + koff + c * 8);
        }
        __half* d1 = dst + 8192;
        __half* d3 = dst + 12288;
        #pragma unroll
        for (int i = 0; i < 4; ++i) {             // B1,B3: 64 rows x 8 chunks
            int idx = tid + 128 * i, r = idx >> 3, c = idx & 7;
            cp16(d1 + r * 64 + ((c ^ (r & 7)) << 3), B1 + (size_t)r * D_ + koff + c * 8);
            cp16(d3 + r * 64 + ((c ^ (r & 7)) << 3), B3 + (size_t)r * D_ + koff + c * 8);
        }
        asm volatile("cp.async.commit_group;" ::: "memory");
    };

    uint32_t a[2][4][4], b1f[2][4][2], b3f[2][4][2];
    auto ldfrag = [&](int kk, int pb, uint32_t soff) {
        #pragma unroll
        for (int mi = 0; mi < 4; ++mi)
            ldm_x4(a[pb][mi][0], a[pb][mi][1], a[pb][mi][2], a[pb][mi][3],
                   aA[kk] + soff + mi * 2048u);
        #pragma unroll
        for (int j = 0; j < 2; ++j) {
            ldm_x4(b1f[pb][2*j][0], b1f[pb][2*j][1], b1f[pb][2*j+1][0], b1f[pb][2*j+1][1],
                   bA[kk] + soff + j * 2048u);
            ldm_x4(b3f[pb][2*j][0], b3f[pb][2*j][1], b3f[pb][2*j+1][0], b3f[pb][2*j+1][1],
                   bA[kk] + soff + 8192u + j * 2048u);
        }
    };

    issue(0, 0); issue(1, 1);
    int cs = 0;
    for (int kt = 0; kt < KIT; ++kt) {
        if (kt + 1 < KIT) asm volatile("cp.async.wait_group 1;" ::: "memory");
        else              asm volatile("cp.async.wait_group 0;" ::: "memory");
        __syncthreads();
        if (kt + 2 < KIT) { int ns = cs + 2; if (ns >= 3) ns -= 3; issue(ns, kt + 2); }
        const uint32_t soff = (uint32_t)cs * STG_BYTES;
        ldfrag(0, 0, soff);
        #pragma unroll
        for (int kk = 0; kk < 4; ++kk) {
            const int cb = kk & 1;
            if (kk < 3) ldfrag(kk + 1, cb ^ 1, soff);
            #pragma unroll
            for (int mi = 0; mi < 4; ++mi)
                #pragma unroll
                for (int nj = 0; nj < 4; ++nj) {
                    mma_f16(c1[mi][nj], a[cb][mi], b1f[cb][nj]);
                    mma_f16(c3[mi][nj], a[cb][mi], b3f[cb][nj]);
                }
        }
        if (++cs == 3) cs = 0;
    }

    // epilogue: h = fp16(silu(c1)*c3), plain row-major
    #pragma unroll
    for (int mi = 0; mi < 4; ++mi)
        #pragma unroll
        for (int nj = 0; nj < 4; ++nj) {
            int r0 = m0 + m_off + 16 * mi + g;
            int col = n0 + n_off + 8 * nj + 2 * t;
            uint32_t v0 = f22h(silu(c1[mi][nj][0]) * c3[mi][nj][0],
                               silu(c1[mi][nj][1]) * c3[mi][nj][1]);
            uint32_t v1 = f22h(silu(c1[mi][nj][2]) * c3[mi][nj][2],
                               silu(c1[mi][nj][3]) * c3[mi][nj][3]);
            *(uint32_t*)(g_h + (size_t)r0 * H_ + col)       = v0;
            *(uint32_t*)(g_h + (size_t)(r0 + 8) * H_ + col) = v1;
        }
}

// ---------------- GEMM2: out = h @ w2^T ---------------------------------------
// CTA 128M x 128N, BK=64, K=1024; 128 thr (4 warps, 64x64)
// grid 2048 = e(8) x mt(16) x nt(16); stage: A 16KB | B 16KB
__global__ void __launch_bounds__(128, 2) moe_gemm2(float* __restrict__ out) {
    extern __shared__ __half sm[];
    const uint32_t sb = smem_u32(sm);
    const int tid = threadIdx.x, lane = tid & 31, wid = tid >> 5;
    const int g = lane >> 2, t = lane & 3, s7 = lane & 7;
    const int bx = blockIdx.x;
    const int e = bx >> 8, mt = (bx >> 4) & 15, nt = bx & 15;
    const int m0 = e * 2048 + mt * 128, n0 = nt * 128;
    const __half* A = g_h  + (size_t)m0 * H_;
    const __half* B = g_w2 + ((size_t)e * D_ + n0) * H_;
    const int KIT = H_ / 64;  // 16
    const int m_off = (wid & 1) * 64, n_off = (wid >> 1) * 64;

    uint32_t aA[4], bA[4];
    #pragma unroll
    for (int kk = 0; kk < 4; ++kk) {
        aA[kk] = sb + (uint32_t)(m_off + (lane & 15)) * 128u
                    + 16u * ((((lane >> 4) | (kk << 1)) ^ s7));
        bA[kk] = sb + 16384u + (uint32_t)(n_off + 8 * (lane >> 4) + s7) * 128u
                    + 16u * (((((lane >> 3) & 1) | (kk << 1)) ^ s7));
    }

    float cc[4][8][4];
    #pragma unroll
    for (int i = 0; i < 4; ++i)
        #pragma unroll
        for (int j = 0; j < 8; ++j)
            #pragma unroll
            for (int q = 0; q < 4; ++q) cc[i][j][q] = 0.f;

    auto issue = [&](int s, int kt) {
        __half* dst = sm + (size_t)s * (STG_BYTES / 2);
        const int koff = kt * 64;
        #pragma unroll
        for (int i = 0; i < 8; ++i) {             // A: 128 x 8 chunks
            int idx = tid + 128 * i, r = idx >> 3, c = idx & 7;
            cp16(dst + r * 64 + ((c ^ (r & 7)) << 3), A + (size_t)r * H_ + koff + c * 8);
        }
        __half* db = dst + 8192;
        #pragma unroll
        for (int i = 0; i < 8; ++i) {             // B: 128 x 8 chunks
            int idx = tid + 128 * i, r = idx >> 3, c = idx & 7;
            cp16(db + r * 64 + ((c ^ (r & 7)) << 3), B + (size_t)r * H_ + koff + c * 8);
        }
        asm volatile("cp.async.commit_group;" ::: "memory");
    };

    uint32_t a[2][4][4], bf[2][8][2];
    auto ldfrag = [&](int kk, int pb, uint32_t soff) {
        #pragma unroll
        for (int mi = 0; mi < 4; ++mi)
            ldm_x4(a[pb][mi][0], a[pb][mi][1], a[pb][mi][2], a[pb][mi][3],
                   aA[kk] + soff + mi * 2048u);
        #pragma unroll
        for (int j = 0; j < 4; ++j)
            ldm_x4(bf[pb][2*j][0], bf[pb][2*j][1], bf[pb][2*j+1][0], bf[pb][2*j+1][1],
                   bA[kk] + soff + j * 2048u);
    };

    issue(0, 0); issue(1, 1);
    int cs = 0;
    for (int kt = 0; kt < KIT; ++kt) {
        if (kt + 1 < KIT) asm volatile("cp.async.wait_group 1;" ::: "memory");
        else              asm volatile("cp.async.wait_group 0;" ::: "memory");
        __syncthreads();
        if (kt + 2 < KIT) { int ns = cs + 2; if (ns >= 3) ns -= 3; issue(ns, kt + 2); }
        const uint32_t soff = (uint32_t)cs * STG_BYTES;
        ldfrag(0, 0, soff);
        #pragma unroll
        for (int kk = 0; kk < 4; ++kk) {
            const int cb = kk & 1;
            if (kk < 3) ldfrag(kk + 1, cb ^ 1, soff);
            #pragma unroll
            for (int mi = 0; mi < 4; ++mi)
                #pragma unroll
                for (int nj = 0; nj < 8; ++nj)
                    mma_f16(cc[mi][nj], a[cb][mi], bf[cb][nj]);
        }
        if (++cs == 3) cs = 0;
    }

    #pragma unroll
    for (int mi = 0; mi < 4; ++mi)
        #pragma unroll
        for (int nj = 0; nj < 8; ++nj) {
            int r0 = m0 + m_off + 16 * mi + g;
            int col = n0 + n_off + 8 * nj + 2 * t;
            float2 v;
            v.x = cc[mi][nj][0]; v.y = cc[mi][nj][1];
            *(float2*)(out + (size_t)r0 * D_ + col) = v;
            v.x = cc[mi][nj][2]; v.y = cc[mi][nj][3];
            *(float2*)(out + (size_t)(r0 + 8) * D_ + col) = v;
        }
}

// ---------------- launch ----------------
extern "C" void kernel_launch(void* const* d_in, const int* in_sizes, int n_in,
                              void* d_out, int out_size) {
    const float4* x  = (const float4*)d_in[0];
    const float4* w1 = (const float4*)d_in[2];
    const float4* w2 = (const float4*)d_in[3];
    const float4* w3 = (const float4*)d_in[4];
    float* out = (float*)d_out;

    const size_t GX = (size_t)T_ * D_ / 8;
    const size_t GW = (size_t)E_ * H_ * D_ / 8;
    int nblk = (int)((GX + 2 * GW + 255) / 256);   // x, w1, w3 only

    pack_xw13<<<nblk, 256>>>(x, w1, w3);

    cudaFuncSetAttribute(moe_gemm1, cudaFuncAttributeMaxDynamicSharedMemorySize, SMEM_SZ);
    cudaFuncSetAttribute(moe_gemm2, cudaFuncAttributeMaxDynamicSharedMemorySize, SMEM_SZ);

    moe_gemm1<<<2560, 128, SMEM_SZ>>>(w2);   // 2048 gemm tiles + 512 w2-pack blocks
    moe_gemm2<<<2048, 128, SMEM_SZ>>>(out);
}